// round 6
// baseline (speedup 1.0000x reference)
#include <cuda_runtime.h>
#include <cuda_fp16.h>
#include <cuda_bf16.h>
#include <mma.h>
#include <stdint.h>

using namespace nvcuda;

#define T_ROWS   256
#define K_DIM    8192
#define M_DIM    8192
#define N_CODES  1024
#define GP_ELEMS 1816   // 227 * 8

// scratch (device globals: allocation-free per harness rules)
__device__ __half  g_gp[2048];               // canonical fp16 codebook
__device__ __half  g_xh[T_ROWS * K_DIM];     // 4 MB
__device__ float   g_z [T_ROWS * M_DIM];     // 8 MB

__device__ __forceinline__ uint32_t smem_u32(const void* p) {
    uint32_t a;
    asm("{ .reg .u64 t; cvta.to.shared.u64 t, %1; cvt.u32.u64 %0, t; }"
        : "=r"(a) : "l"(p));
    return a;
}
__device__ __forceinline__ void cp_async16(uint32_t dst, const void* src) {
    asm volatile("cp.async.cg.shared.global [%0], [%1], 16;" :: "r"(dst), "l"(src));
}

// ---------------------------------------------------------------------------
// K0: normalize grid_part to fp16 regardless of delivered dtype.
// ---------------------------------------------------------------------------
__global__ void prep_gp_kernel(const void* __restrict__ gp_raw)
{
    const uint32_t w0 = *(const uint32_t*)gp_raw;
    const int i = threadIdx.x + blockIdx.x * blockDim.x;
    if (i >= GP_ELEMS) return;
    float v;
    if (w0 == 0x3F000000u)        v = ((const float*)gp_raw)[i];
    else if (w0 == 0x3F003F00u)   v = __bfloat162float(((const __nv_bfloat16*)gp_raw)[i]);
    else                          v = __half2float(((const __half*)gp_raw)[i]);
    g_gp[i] = __float2half(v);
}

// ---------------------------------------------------------------------------
// K1: x = SU*x ; FWHT(8192) ; /(sqrt(8192)*1024) ; fp16
// ---------------------------------------------------------------------------
__global__ void fwht_in_kernel(const float* __restrict__ x,
                               const float* __restrict__ SU)
{
    __shared__ float s[K_DIM];
    const int row = blockIdx.x;
    const float* xr = x + (size_t)row * K_DIM;
    for (int i = threadIdx.x; i < K_DIM; i += 256)
        s[i] = xr[i] * SU[i];
    __syncthreads();
    for (int h = 1; h < K_DIM; h <<= 1) {
        #pragma unroll 1
        for (int j = 0; j < 16; j++) {
            int i   = threadIdx.x + j * 256;
            int idx = ((i & ~(h - 1)) << 1) | (i & (h - 1));
            float a = s[idx], b = s[idx + h];
            s[idx]     = a + b;
            s[idx + h] = a - b;
        }
        __syncthreads();
    }
    const float c = 1.0789593218788508e-05f;   // 1/(sqrt(8192)*1024)
    __half* o = g_xh + (size_t)row * K_DIM;
    for (int i = threadIdx.x; i < K_DIM; i += 256)
        o[i] = __float2half(s[i] * c);
}

// ---------------------------------------------------------------------------
// K3: fused dequant + wmma GEMM
// block: M=256 (ALL x rows) x N=64 (W rows) -> each W element decoded ONCE.
// K-chunk 64; 3-stage cp.async pipeline; sign-mask LUT in smem.
// 8 warps stacked in m: warp tile 32(m) x 64(n).
// ---------------------------------------------------------------------------
#define STAGES      3
#define NCHUNK      128            // 8192 / 64
#define BNT         64
#define LDSM        72             // 64 + 8 pad halves; 144B row stride
#define A_BYTES     (256 * 144)    // 36864
#define B_BYTES     (64 * 144)     // 9216
#define STAGE_BYTES (A_BYTES + B_BYTES)
#define SM_CB       0              // codebook 227*16B
#define SM_LUT      3712           // sign LUT 256*16B
#define SM_STAGE    7808
#define SMEM_GEMM   (SM_STAGE + STAGES * STAGE_BYTES)   // 146048

__global__ void __launch_bounds__(256, 1) gemm_fused_kernel(const int* __restrict__ Q)
{
    extern __shared__ char smem[];
    const uint32_t sb = smem_u32(smem);
    const int tid = threadIdx.x;
    const int warpId = tid >> 5;          // 0..7 -> 32 m-rows each
    const int n0 = blockIdx.x * BNT;

    if (tid < 227)
        *(uint4*)(smem + SM_CB + tid * 16) = *(const uint4*)(g_gp + tid * 8);
    // sign LUT: LUT[f].j = sign masks for codes 2j,2j+1
    {
        uint32_t f = tid & 255;
        uint4 m;
        m.x = ((f & 1)  ? 0x8000u : 0u) | ((f & 2)   ? 0x80000000u : 0u);
        m.y = ((f & 4)  ? 0x8000u : 0u) | ((f & 8)   ? 0x80000000u : 0u);
        m.z = ((f & 16) ? 0x8000u : 0u) | ((f & 32)  ? 0x80000000u : 0u);
        m.w = ((f & 64) ? 0x8000u : 0u) | ((f & 128) ? 0x80000000u : 0u);
        *(uint4*)(smem + SM_LUT + f * 16) = m;
    }
    __syncthreads();

    // B decode mapping: 512 codes/chunk, 2 per thread
    const int q_row = tid >> 2;           // 0..63
    const int q_j0  = (tid & 3) * 2;      // 0,2,4,6
    const int2* qptr = (const int2*)(Q + (size_t)(n0 + q_row) * N_CODES) + (q_j0 >> 1);
    // (qptr[c*4] = codes {c*8+q_j0, c*8+q_j0+1})

    wmma::fragment<wmma::accumulator, 16, 16, 16, float> acc[2][4];
    #pragma unroll
    for (int i = 0; i < 2; i++)
        #pragma unroll
        for (int j = 0; j < 4; j++)
            wmma::fill_fragment(acc[i][j], 0.0f);

    auto fill = [&](int c, int2 q) {
        const int s = c % STAGES;
        const uint32_t abase = sb + SM_STAGE + s * STAGE_BYTES;
        // A tile: 256 rows x 128B
        #pragma unroll
        for (int u = 0; u < 8; u++) {
            int lin = tid + u * 256;            // 0..2047 16B units
            int row = lin >> 3, c16 = lin & 7;
            cp_async16(abase + row * 144 + c16 * 16,
                       g_xh + (size_t)row * K_DIM + c * 64 + c16 * 8);
        }
        // B tile: decode 2 codes
        char* bb = smem + SM_STAGE + s * STAGE_BYTES + A_BYTES;
        const int qs[2] = {q.x, q.y};
        #pragma unroll
        for (int e = 0; e < 2; e++) {
            int idx = qs[e] + 32768;
            const uint4 cb = *(const uint4*)(smem + SM_CB  + (idx & 255) * 16);
            const uint4 sm = *(const uint4*)(smem + SM_LUT + (idx >> 8)  * 16);
            uint4 o;
            o.x = cb.x ^ sm.x;  o.y = cb.y ^ sm.y;
            o.z = cb.z ^ sm.z;  o.w = cb.w ^ sm.w;
            *(uint4*)(bb + q_row * 144 + (q_j0 + e) * 16) = o;
        }
    };

    fill(0, qptr[0]);
    asm volatile("cp.async.commit_group;" ::: "memory");
    fill(1, qptr[4]);
    asm volatile("cp.async.commit_group;" ::: "memory");

    for (int i = 0; i < NCHUNK; i++) {
        int2 qn = {0, 0};
        if (i + 2 < NCHUNK) qn = qptr[(i + 2) * 4];

        asm volatile("cp.async.wait_group 1;" ::: "memory");
        __syncthreads();

        const int s = i % STAGES;
        const __half* As = (const __half*)(smem + SM_STAGE + s * STAGE_BYTES);
        const __half* Bs = (const __half*)(smem + SM_STAGE + s * STAGE_BYTES + A_BYTES);
        #pragma unroll
        for (int kk = 0; kk < 4; kk++) {
            wmma::fragment<wmma::matrix_a, 16, 16, 16, __half, wmma::row_major> a[2];
            wmma::fragment<wmma::matrix_b, 16, 16, 16, __half, wmma::col_major> b[4];
            #pragma unroll
            for (int ii = 0; ii < 2; ii++)
                wmma::load_matrix_sync(a[ii], &As[(warpId * 32 + ii * 16) * LDSM + kk * 16], LDSM);
            #pragma unroll
            for (int jj = 0; jj < 4; jj++)
                wmma::load_matrix_sync(b[jj], &Bs[(jj * 16) * LDSM + kk * 16], LDSM);
            #pragma unroll
            for (int ii = 0; ii < 2; ii++)
                #pragma unroll
                for (int jj = 0; jj < 4; jj++)
                    wmma::mma_sync(acc[ii][jj], a[ii], b[jj], acc[ii][jj]);
        }
        __syncthreads();

        if (i + 2 < NCHUNK) fill(i + 2, qn);
        asm volatile("cp.async.commit_group;" ::: "memory");
    }

    #pragma unroll
    for (int ii = 0; ii < 2; ii++)
        #pragma unroll
        for (int jj = 0; jj < 4; jj++)
            wmma::store_matrix_sync(
                &g_z[(size_t)(warpId * 32 + ii * 16) * M_DIM + n0 + jj * 16],
                acc[ii][jj], M_DIM, wmma::mem_row_major);
}

// ---------------------------------------------------------------------------
// K4: out = SV * fwht(z) * (Wscale*1024/sqrt(8192))
// ---------------------------------------------------------------------------
__global__ void fwht_out_kernel(const float* __restrict__ SV,
                                const float* __restrict__ Wscale,
                                float* __restrict__ out)
{
    __shared__ float s[M_DIM];
    const int row = blockIdx.x;
    const float* zr = g_z + (size_t)row * M_DIM;
    for (int i = threadIdx.x; i < M_DIM; i += 256)
        s[i] = zr[i];
    __syncthreads();
    for (int h = 1; h < M_DIM; h <<= 1) {
        #pragma unroll 1
        for (int j = 0; j < 16; j++) {
            int i   = threadIdx.x + j * 256;
            int idx = ((i & ~(h - 1)) << 1) | (i & (h - 1));
            float a = s[idx], b = s[idx + h];
            s[idx]     = a + b;
            s[idx + h] = a - b;
        }
        __syncthreads();
    }
    const float c = Wscale[0] * 11.313708498984761f;  // 1024/sqrt(8192)
    float* o = out + (size_t)row * M_DIM;
    for (int i = threadIdx.x; i < M_DIM; i += 256)
        o[i] = s[i] * c * SV[i];
}

// ---------------------------------------------------------------------------
extern "C" void kernel_launch(void* const* d_in, const int* in_sizes, int n_in,
                              void* d_out, int out_size)
{
    const float* x  = nullptr;  const int*   Q  = nullptr;
    const float* SU = nullptr;  const float* SV = nullptr;
    const float* Ws = nullptr;  const void*  gp = nullptr;
    for (int i = 0; i < n_in; i++) {
        int s = in_sizes[i];
        if      (s == T_ROWS * K_DIM)   x  = (const float*)d_in[i];
        else if (s == M_DIM * N_CODES)  Q  = (const int*)d_in[i];
        else if (s == 1)                Ws = (const float*)d_in[i];
        else if (s == K_DIM) { if (!SU) SU = (const float*)d_in[i];
                               else     SV = (const float*)d_in[i]; }
        else                            gp = d_in[i];
    }
    float* out = (float*)d_out;

    static bool smem_set = false;
    if (!smem_set) {
        cudaFuncSetAttribute(gemm_fused_kernel,
                             cudaFuncAttributeMaxDynamicSharedMemorySize, SMEM_GEMM);
        smem_set = true;
    }

    prep_gp_kernel<<<8, 256>>>(gp);
    fwht_in_kernel<<<T_ROWS, 256>>>(x, SU);
    gemm_fused_kernel<<<M_DIM / BNT, 256, SMEM_GEMM>>>(Q);
    fwht_out_kernel<<<T_ROWS, 256>>>(SV, Ws, out);
}